// round 1
// baseline (speedup 1.0000x reference)
#include <cuda_runtime.h>
#include <mma.h>
#include <math.h>

using namespace nvcuda;

// Problem constants (B=4, C=8, F=2048, H=512, Hf=1024, NH=8, dh=64)
#define NROWS_Q 8192     // F*B query rows
#define NROWS_K 65536    // F*B*C key/value rows
#define HD      512
#define HFF     1024

// ---------------- scratch (device globals; no allocation allowed) ----------
__device__ float g_Qp[(size_t)NROWS_Q * HD];
__device__ float g_Kp[(size_t)NROWS_K * HD];
__device__ float g_Vp[(size_t)NROWS_K * HD];
__device__ float g_X [(size_t)NROWS_Q * HD];
__device__ float g_Xo[(size_t)NROWS_Q * HD];
__device__ float g_H1[(size_t)NROWS_Q * HD];
__device__ float g_FF[(size_t)NROWS_Q * HFF];
__device__ float g_Y [(size_t)NROWS_Q * HD];

// ---------------- split-tf32 GEMM: C = A[M,K] @ W[N,K]^T + bias (+res)(+relu)
// BM=128, BN=64, BK=32, 256 threads (8 warps in 4x2 grid, 32x32 per warp).
template<bool RELU, bool RES>
__global__ __launch_bounds__(256)
void gemm_tf32(const float* __restrict__ A, const float* __restrict__ W,
               const float* __restrict__ bias, const float* __restrict__ res,
               float* __restrict__ Cout, int M, int N, int K)
{
    constexpr int BM = 128, BN = 64, BK = 32;
    constexpr int LDS = 40;   // smem leading dim for A/B tiles (mult of 8)
    constexpr int LDC = 68;   // smem leading dim for C staging

    __shared__ __align__(16) float smem[BM * LDC];   // 34.8 KB, reused
    float* sA = smem;                 // BM*LDS = 5120 floats
    float* sB = smem + BM * LDS;      // BN*LDS = 2560 floats
    float* sC = smem;                 // BM*LDC = 8704 floats (after K loop)

    const int tid  = threadIdx.x;
    const int warp = tid >> 5;
    const int wm   = warp & 3;        // 0..3  (M direction)
    const int wn   = warp >> 2;       // 0..1  (N direction)
    const int bm0  = blockIdx.y * BM;
    const int bn0  = blockIdx.x * BN;

    wmma::fragment<wmma::accumulator, 16, 16, 8, float> acc[2][2];
    #pragma unroll
    for (int i = 0; i < 2; i++)
        #pragma unroll
        for (int j = 0; j < 2; j++)
            wmma::fill_fragment(acc[i][j], 0.0f);

    const int rr = tid >> 3;          // 0..31
    const int cc = (tid & 7) * 4;     // 0..28

    for (int k0 = 0; k0 < K; k0 += BK) {
        // load A tile [128,32]
        #pragma unroll
        for (int i = 0; i < 4; i++) {
            float4 v = *reinterpret_cast<const float4*>(
                A + (size_t)(bm0 + rr + i * 32) * K + k0 + cc);
            float* d = sA + (rr + i * 32) * LDS + cc;
            d[0] = v.x; d[1] = v.y; d[2] = v.z; d[3] = v.w;
        }
        // load W tile [64,32]  (W row-major [N,K] == B^T; use as col_major B)
        #pragma unroll
        for (int i = 0; i < 2; i++) {
            float4 v = *reinterpret_cast<const float4*>(
                W + (size_t)(bn0 + rr + i * 32) * K + k0 + cc);
            float* d = sB + (rr + i * 32) * LDS + cc;
            d[0] = v.x; d[1] = v.y; d[2] = v.z; d[3] = v.w;
        }
        __syncthreads();

        #pragma unroll
        for (int kk = 0; kk < BK; kk += 8) {
            wmma::fragment<wmma::matrix_a, 16, 16, 8, wmma::precision::tf32, wmma::row_major> ah[2], al[2];
            wmma::fragment<wmma::matrix_b, 16, 16, 8, wmma::precision::tf32, wmma::col_major> bh[2], bl[2];

            #pragma unroll
            for (int i = 0; i < 2; i++) {
                wmma::load_matrix_sync(ah[i], sA + (wm * 32 + i * 16) * LDS + kk, LDS);
                #pragma unroll
                for (int e = 0; e < ah[i].num_elements; e++) {
                    float x  = ah[i].x[e];
                    float hi = wmma::__float_to_tf32(x);
                    ah[i].x[e] = hi;
                    al[i].x[e] = wmma::__float_to_tf32(x - hi);
                }
            }
            #pragma unroll
            for (int j = 0; j < 2; j++) {
                wmma::load_matrix_sync(bh[j], sB + (wn * 32 + j * 16) * LDS + kk, LDS);
                #pragma unroll
                for (int e = 0; e < bh[j].num_elements; e++) {
                    float x  = bh[j].x[e];
                    float hi = wmma::__float_to_tf32(x);
                    bh[j].x[e] = hi;
                    bl[j].x[e] = wmma::__float_to_tf32(x - hi);
                }
            }
            #pragma unroll
            for (int i = 0; i < 2; i++)
                #pragma unroll
                for (int j = 0; j < 2; j++) {
                    wmma::mma_sync(acc[i][j], ah[i], bh[j], acc[i][j]);
                    wmma::mma_sync(acc[i][j], al[i], bh[j], acc[i][j]);
                    wmma::mma_sync(acc[i][j], ah[i], bl[j], acc[i][j]);
                }
        }
        __syncthreads();
    }

    // stage accumulators through smem so the epilogue knows (m,n) coordinates
    #pragma unroll
    for (int i = 0; i < 2; i++)
        #pragma unroll
        for (int j = 0; j < 2; j++)
            wmma::store_matrix_sync(sC + (wm * 32 + i * 16) * LDC + wn * 32 + j * 16,
                                    acc[i][j], LDC, wmma::mem_row_major);
    __syncthreads();

    for (int idx = tid; idx < BM * BN; idx += 256) {
        int m = idx >> 6;
        int n = idx & 63;
        float v = sC[m * LDC + n] + bias[bn0 + n];
        if (RES)  v += res[(size_t)(bm0 + m) * N + bn0 + n];
        if (RELU) v  = fmaxf(v, 0.0f);
        Cout[(size_t)(bm0 + m) * N + bn0 + n] = v;
    }
}

// ---------------- attention: one block per query row, one warp per head -----
__global__ __launch_bounds__(256)
void attn_kernel()
{
    const int r = blockIdx.x;               // query row 0..8191
    const int w = threadIdx.x >> 5;         // head 0..7
    const int l = threadIdx.x & 31;

    const float* q = g_Qp + (size_t)r * HD + w * 64;
    const float q0 = q[l];
    const float q1 = q[l + 32];

    const size_t kbase = (size_t)r * 8 * HD + w * 64;

    float s[8];
    #pragma unroll
    for (int c = 0; c < 8; c++) {
        const float* kp = g_Kp + kbase + (size_t)c * HD;
        float p = q0 * kp[l] + q1 * kp[l + 32];
        #pragma unroll
        for (int o = 16; o; o >>= 1) p += __shfl_xor_sync(0xffffffffu, p, o);
        s[c] = p;
    }

    float mx = s[0];
    #pragma unroll
    for (int c = 1; c < 8; c++) mx = fmaxf(mx, s[c]);

    float e[8], sum = 0.0f;
    #pragma unroll
    for (int c = 0; c < 8; c++) { e[c] = expf((s[c] - mx) * 0.125f); sum += e[c]; }
    const float inv = 1.0f / sum;

    float x0 = 0.0f, x1 = 0.0f;
    #pragma unroll
    for (int c = 0; c < 8; c++) {
        const float* vp = g_Vp + kbase + (size_t)c * HD;
        const float a = e[c] * inv;
        x0 += a * vp[l];
        x1 += a * vp[l + 32];
    }
    g_X[(size_t)r * HD + w * 64 + l]      = x0;
    g_X[(size_t)r * HD + w * 64 + l + 32] = x1;
}

// ---------------- LayerNorm: one block (256 thr) per row of 512 -------------
__global__ __launch_bounds__(256)
void ln_kernel(const float* __restrict__ X, const float* __restrict__ gw,
               const float* __restrict__ bw, float* __restrict__ Out)
{
    const int r = blockIdx.x;
    const int t = threadIdx.x;
    const float* x = X + (size_t)r * HD;
    const float v0 = x[t];
    const float v1 = x[t + 256];

    __shared__ float red[8];
    __shared__ float s_mean, s_rstd;

    float s = v0 + v1;
    #pragma unroll
    for (int o = 16; o; o >>= 1) s += __shfl_xor_sync(0xffffffffu, s, o);
    if ((t & 31) == 0) red[t >> 5] = s;
    __syncthreads();
    if (t < 32) {
        float z = (t < 8) ? red[t] : 0.0f;
        #pragma unroll
        for (int o = 4; o; o >>= 1) z += __shfl_xor_sync(0xffffffffu, z, o);
        if (t == 0) s_mean = z * (1.0f / 512.0f);
    }
    __syncthreads();
    const float mean = s_mean;
    const float d0 = v0 - mean, d1 = v1 - mean;

    float qv = d0 * d0 + d1 * d1;
    #pragma unroll
    for (int o = 16; o; o >>= 1) qv += __shfl_xor_sync(0xffffffffu, qv, o);
    if ((t & 31) == 0) red[t >> 5] = qv;
    __syncthreads();
    if (t < 32) {
        float z = (t < 8) ? red[t] : 0.0f;
        #pragma unroll
        for (int o = 4; o; o >>= 1) z += __shfl_xor_sync(0xffffffffu, z, o);
        if (t == 0) s_rstd = rsqrtf(z * (1.0f / 512.0f) + 1e-5f);
    }
    __syncthreads();
    const float rs = s_rstd;
    Out[(size_t)r * HD + t]       = d0 * rs * gw[t]       + bw[t];
    Out[(size_t)r * HD + t + 256] = d1 * rs * gw[t + 256] + bw[t + 256];
}

// ---------------- launch ----------------------------------------------------
extern "C" void kernel_launch(void* const* d_in, const int* in_sizes, int n_in,
                              void* d_out, int out_size)
{
    (void)in_sizes; (void)n_in; (void)out_size;
    const float* query = (const float*)d_in[0];
    const float* key   = (const float*)d_in[1];
    const float* value = (const float*)d_in[2];
    const float* Wq    = (const float*)d_in[3];
    const float* bq    = (const float*)d_in[4];
    const float* Wk    = (const float*)d_in[5];
    const float* bk    = (const float*)d_in[6];
    const float* Wv    = (const float*)d_in[7];
    const float* bv    = (const float*)d_in[8];
    const float* Wo    = (const float*)d_in[9];
    const float* bo    = (const float*)d_in[10];
    const float* ln1_g = (const float*)d_in[11];
    const float* ln1_b = (const float*)d_in[12];
    const float* W1    = (const float*)d_in[13];
    const float* b1    = (const float*)d_in[14];
    const float* W2    = (const float*)d_in[15];
    const float* b2    = (const float*)d_in[16];
    const float* ln2_g = (const float*)d_in[17];
    const float* ln2_b = (const float*)d_in[18];
    float* out = (float*)d_out;

    float *Qp, *Kp, *Vp, *X, *Xo, *H1, *FF, *Y;
    cudaGetSymbolAddress((void**)&Qp, g_Qp);
    cudaGetSymbolAddress((void**)&Kp, g_Kp);
    cudaGetSymbolAddress((void**)&Vp, g_Vp);
    cudaGetSymbolAddress((void**)&X,  g_X);
    cudaGetSymbolAddress((void**)&Xo, g_Xo);
    cudaGetSymbolAddress((void**)&H1, g_H1);
    cudaGetSymbolAddress((void**)&FF, g_FF);
    cudaGetSymbolAddress((void**)&Y,  g_Y);

    const dim3 blk(256);

    // Projections: Qp/Kp/Vp
    gemm_tf32<false, false><<<dim3(HD / 64, NROWS_Q / 128), blk>>>(
        query, Wq, bq, nullptr, Qp, NROWS_Q, HD, HD);
    gemm_tf32<false, false><<<dim3(HD / 64, NROWS_K / 128), blk>>>(
        key, Wk, bk, nullptr, Kp, NROWS_K, HD, HD);
    gemm_tf32<false, false><<<dim3(HD / 64, NROWS_K / 128), blk>>>(
        value, Wv, bv, nullptr, Vp, NROWS_K, HD, HD);

    // Attention (softmax over C=8 per head)
    attn_kernel<<<NROWS_Q, blk>>>();

    // Output projection + residual(q), then LN1
    gemm_tf32<false, true><<<dim3(HD / 64, NROWS_Q / 128), blk>>>(
        X, Wo, bo, query, Xo, NROWS_Q, HD, HD);
    ln_kernel<<<NROWS_Q, blk>>>(Xo, ln1_g, ln1_b, H1);

    // FFN
    gemm_tf32<true, false><<<dim3(HFF / 64, NROWS_Q / 128), blk>>>(
        H1, W1, b1, nullptr, FF, NROWS_Q, HFF, HD);
    gemm_tf32<false, true><<<dim3(HD / 64, NROWS_Q / 128), blk>>>(
        FF, W2, b2, H1, Y, NROWS_Q, HD, HFF);

    // LN2 -> output (flat layout already matches [B,F,H])
    ln_kernel<<<NROWS_Q, blk>>>(Y, ln2_g, ln2_b, out);
}

// round 3
// speedup vs baseline: 2.4416x; 2.4416x over previous
#include <cstdint>
#include <cuda_runtime.h>
#include <cuda_bf16.h>
#include <mma.h>
#include <math.h>

using namespace nvcuda;

// Problem constants (B=4, C=8, F=2048, H=512, Hf=1024, NH=8, dh=64)
#define NROWS_Q 8192
#define NROWS_K 65536
#define HD      512
#define HFF     1024

typedef __nv_bfloat16 bf16;

// ---------------- scratch (device globals; no allocation allowed) -----------
// bf16 hi/lo planes of GEMM A-operands
__device__ bf16 g_qsh[(size_t)NROWS_Q * HD];
__device__ bf16 g_qsl[(size_t)NROWS_Q * HD];
__device__ bf16 g_ksh[(size_t)NROWS_K * HD];
__device__ bf16 g_ksl[(size_t)NROWS_K * HD];
__device__ bf16 g_vsh[(size_t)NROWS_K * HD];
__device__ bf16 g_vsl[(size_t)NROWS_K * HD];
__device__ bf16 g_Xh [(size_t)NROWS_Q * HD];
__device__ bf16 g_Xl [(size_t)NROWS_Q * HD];
__device__ bf16 g_H1h[(size_t)NROWS_Q * HD];
__device__ bf16 g_H1l[(size_t)NROWS_Q * HD];
__device__ bf16 g_FFh[(size_t)NROWS_Q * HFF];
__device__ bf16 g_FFl[(size_t)NROWS_Q * HFF];
// weight hi/lo planes
__device__ bf16 g_Wqh[HD*HD], g_Wql[HD*HD];
__device__ bf16 g_Wkh[HD*HD], g_Wkl[HD*HD];
__device__ bf16 g_Wvh[HD*HD], g_Wvl[HD*HD];
__device__ bf16 g_Woh[HD*HD], g_Wol[HD*HD];
__device__ bf16 g_W1h[HFF*HD], g_W1l[HFF*HD];
__device__ bf16 g_W2h[HD*HFF], g_W2l[HD*HFF];
// fp32 intermediates
__device__ float g_Qp[(size_t)NROWS_Q * HD];
__device__ float g_Kp[(size_t)NROWS_K * HD];
__device__ float g_Vp[(size_t)NROWS_K * HD];
__device__ float g_Xo[(size_t)NROWS_Q * HD];
__device__ float g_H1[(size_t)NROWS_Q * HD];
__device__ float g_Y [(size_t)NROWS_Q * HD];

// ---------------- helpers ----------------------------------------------------
__device__ __forceinline__ void cp16(void* s, const void* g) {
    unsigned int sa = (unsigned int)__cvta_generic_to_shared(s);
    asm volatile("cp.async.cg.shared.global [%0], [%1], 16;\n" :: "r"(sa), "l"(g));
}
__device__ __forceinline__ void cp_commit() { asm volatile("cp.async.commit_group;\n"); }
template<int N> __device__ __forceinline__ void cp_wait() {
    asm volatile("cp.async.wait_group %0;\n" :: "n"(N));
}

// ---------------- split: fp32 -> bf16 hi/lo ---------------------------------
__global__ __launch_bounds__(256)
void split_kernel(const float* __restrict__ s, bf16* __restrict__ h,
                  bf16* __restrict__ l, int n)
{
    int i = (blockIdx.x * 256 + threadIdx.x) * 4;
    if (i >= n) return;
    float4 v = *reinterpret_cast<const float4*>(s + i);
    bf16 h0 = __float2bfloat16_rn(v.x);
    bf16 h1 = __float2bfloat16_rn(v.y);
    bf16 h2 = __float2bfloat16_rn(v.z);
    bf16 h3 = __float2bfloat16_rn(v.w);
    bf16 l0 = __float2bfloat16_rn(v.x - __bfloat162float(h0));
    bf16 l1 = __float2bfloat16_rn(v.y - __bfloat162float(h1));
    bf16 l2 = __float2bfloat16_rn(v.z - __bfloat162float(h2));
    bf16 l3 = __float2bfloat16_rn(v.w - __bfloat162float(h3));
    __nv_bfloat162 ph0; ph0.x = h0; ph0.y = h1;
    __nv_bfloat162 ph1; ph1.x = h2; ph1.y = h3;
    __nv_bfloat162 pl0; pl0.x = l0; pl0.y = l1;
    __nv_bfloat162 pl1; pl1.x = l2; pl1.y = l3;
    *reinterpret_cast<__nv_bfloat162*>(h + i)     = ph0;
    *reinterpret_cast<__nv_bfloat162*>(h + i + 2) = ph1;
    *reinterpret_cast<__nv_bfloat162*>(l + i)     = pl0;
    *reinterpret_cast<__nv_bfloat162*>(l + i + 2) = pl1;
}

// ---------------- bf16-split GEMM: C = A[M,K] @ W[N,K]^T + bias -------------
// hi*hi + hi*lo + lo*hi (lo*lo dropped, ~2^-18 relative).
// BM=128, BN=64, BK=32, 256 threads, 8 warps (4 M x 2 N), 32x32 per warp.
// Double-buffered smem via cp.async.
template<bool RELU, bool RES, bool OUTF, bool SPLIT>
__global__ __launch_bounds__(256)
void gemm_bf16s(const bf16* __restrict__ Ah, const bf16* __restrict__ Al,
                const bf16* __restrict__ Wh, const bf16* __restrict__ Wl,
                const float* __restrict__ bias, const float* __restrict__ res,
                float* __restrict__ Cout, bf16* __restrict__ Oh,
                bf16* __restrict__ Ol, int M, int N, int K)
{
    constexpr int BM = 128, BN = 64, BK = 32;
    constexpr int LDA = 40;                 // bf16 elems, 80B rows (conflict-free)
    constexpr int ASZ = BM * LDA;           // elems per A plane
    constexpr int BSZ = BN * LDA;
    constexpr int STAGE_ELEMS = 2 * ASZ + 2 * BSZ;
    constexpr int LDC = 68;

    extern __shared__ __align__(16) unsigned char smem_raw[];
    bf16* smem = reinterpret_cast<bf16*>(smem_raw);

    const int tid  = threadIdx.x;
    const int warp = tid >> 5;
    const int wm   = warp & 3;
    const int wn   = warp >> 2;
    const int bm0  = blockIdx.y * BM;
    const int bn0  = blockIdx.x * BN;
    const int NK   = K / BK;

    wmma::fragment<wmma::accumulator, 16, 16, 16, float> acc[2][2];
    #pragma unroll
    for (int i = 0; i < 2; i++)
        #pragma unroll
        for (int j = 0; j < 2; j++)
            wmma::fill_fragment(acc[i][j], 0.0f);

    // --- async stage loader -------------------------------------------------
    auto load_stage = [&](int s, int k0) {
        bf16* dAh = smem + s * STAGE_ELEMS;
        bf16* dAl = dAh + ASZ;
        bf16* dBh = dAl + ASZ;
        bf16* dBl = dBh + BSZ;
        #pragma unroll
        for (int t = 0; t < 2; t++) {               // A: 512 chunks/plane
            int chunk = tid + t * 256;
            int row = chunk >> 2;
            int c   = (chunk & 3) * 8;
            size_t goff = (size_t)(bm0 + row) * K + k0 + c;
            cp16(dAh + row * LDA + c, Ah + goff);
            cp16(dAl + row * LDA + c, Al + goff);
        }
        {                                           // B: 256 chunks/plane
            int row = tid >> 2;
            int c   = (tid & 3) * 8;
            size_t goff = (size_t)(bn0 + row) * K + k0 + c;
            cp16(dBh + row * LDA + c, Wh + goff);
            cp16(dBl + row * LDA + c, Wl + goff);
        }
    };

    load_stage(0, 0);
    cp_commit();

    for (int kt = 0; kt < NK; kt++) {
        if (kt + 1 < NK) {
            load_stage((kt + 1) & 1, (kt + 1) * BK);
            cp_commit();
            cp_wait<1>();
        } else {
            cp_wait<0>();
        }
        __syncthreads();

        const bf16* sAh = smem + (kt & 1) * STAGE_ELEMS;
        const bf16* sAl = sAh + ASZ;
        const bf16* sBh = sAl + ASZ;
        const bf16* sBl = sBh + BSZ;

        #pragma unroll
        for (int kk = 0; kk < BK; kk += 16) {
            wmma::fragment<wmma::matrix_a, 16, 16, 16, bf16, wmma::row_major> ah[2], al[2];
            wmma::fragment<wmma::matrix_b, 16, 16, 16, bf16, wmma::col_major> bh[2], bl[2];
            #pragma unroll
            for (int i = 0; i < 2; i++) {
                wmma::load_matrix_sync(ah[i], sAh + (wm * 32 + i * 16) * LDA + kk, LDA);
                wmma::load_matrix_sync(al[i], sAl + (wm * 32 + i * 16) * LDA + kk, LDA);
            }
            #pragma unroll
            for (int j = 0; j < 2; j++) {
                wmma::load_matrix_sync(bh[j], sBh + (wn * 32 + j * 16) * LDA + kk, LDA);
                wmma::load_matrix_sync(bl[j], sBl + (wn * 32 + j * 16) * LDA + kk, LDA);
            }
            #pragma unroll
            for (int i = 0; i < 2; i++)
                #pragma unroll
                for (int j = 0; j < 2; j++) {
                    wmma::mma_sync(acc[i][j], ah[i], bh[j], acc[i][j]);
                    wmma::mma_sync(acc[i][j], ah[i], bl[j], acc[i][j]);
                    wmma::mma_sync(acc[i][j], al[i], bh[j], acc[i][j]);
                }
        }
        __syncthreads();
    }

    // --- epilogue via smem staging ------------------------------------------
    float* sC = reinterpret_cast<float*>(smem_raw);
    #pragma unroll
    for (int i = 0; i < 2; i++)
        #pragma unroll
        for (int j = 0; j < 2; j++)
            wmma::store_matrix_sync(sC + (wm * 32 + i * 16) * LDC + wn * 32 + j * 16,
                                    acc[i][j], LDC, wmma::mem_row_major);
    __syncthreads();

    for (int idx = tid; idx < BM * BN; idx += 256) {
        int m = idx >> 6;
        int n = idx & 63;
        size_t go = (size_t)(bm0 + m) * N + bn0 + n;
        float v = sC[m * LDC + n] + bias[bn0 + n];
        if (RES)  v += res[go];
        if (RELU) v  = fmaxf(v, 0.0f);
        if (OUTF) Cout[go] = v;
        if (SPLIT) {
            bf16 h = __float2bfloat16_rn(v);
            Oh[go] = h;
            Ol[go] = __float2bfloat16_rn(v - __bfloat162float(h));
        }
    }
}

// ---------------- attention: one block per query row, one warp per head -----
__global__ __launch_bounds__(256)
void attn_kernel()
{
    const int r = blockIdx.x;
    const int w = threadIdx.x >> 5;
    const int l = threadIdx.x & 31;

    const float* q = g_Qp + (size_t)r * HD + w * 64;
    const float q0 = q[l];
    const float q1 = q[l + 32];

    const size_t kbase = (size_t)r * 8 * HD + w * 64;

    float s[8];
    #pragma unroll
    for (int c = 0; c < 8; c++) {
        const float* kp = g_Kp + kbase + (size_t)c * HD;
        float p = q0 * kp[l] + q1 * kp[l + 32];
        #pragma unroll
        for (int o = 16; o; o >>= 1) p += __shfl_xor_sync(0xffffffffu, p, o);
        s[c] = p;
    }

    float mx = s[0];
    #pragma unroll
    for (int c = 1; c < 8; c++) mx = fmaxf(mx, s[c]);

    float e[8], sum = 0.0f;
    #pragma unroll
    for (int c = 0; c < 8; c++) { e[c] = expf((s[c] - mx) * 0.125f); sum += e[c]; }
    const float inv = 1.0f / sum;

    float x0 = 0.0f, x1 = 0.0f;
    #pragma unroll
    for (int c = 0; c < 8; c++) {
        const float* vp = g_Vp + kbase + (size_t)c * HD;
        const float a = e[c] * inv;
        x0 += a * vp[l];
        x1 += a * vp[l + 32];
    }
    size_t o0 = (size_t)r * HD + w * 64 + l;
    bf16 h0 = __float2bfloat16_rn(x0);
    bf16 h1 = __float2bfloat16_rn(x1);
    g_Xh[o0]      = h0;
    g_Xh[o0 + 32] = h1;
    g_Xl[o0]      = __float2bfloat16_rn(x0 - __bfloat162float(h0));
    g_Xl[o0 + 32] = __float2bfloat16_rn(x1 - __bfloat162float(h1));
}

// ---------------- LayerNorm (optionally emits bf16 hi/lo too) ---------------
template<bool SPLIT>
__global__ __launch_bounds__(256)
void ln_kernel(const float* __restrict__ X, const float* __restrict__ gw,
               const float* __restrict__ bw, float* __restrict__ Out,
               bf16* __restrict__ Oh, bf16* __restrict__ Ol)
{
    const int r = blockIdx.x;
    const int t = threadIdx.x;
    const float* x = X + (size_t)r * HD;
    const float v0 = x[t];
    const float v1 = x[t + 256];

    __shared__ float red[8];
    __shared__ float s_mean, s_rstd;

    float s = v0 + v1;
    #pragma unroll
    for (int o = 16; o; o >>= 1) s += __shfl_xor_sync(0xffffffffu, s, o);
    if ((t & 31) == 0) red[t >> 5] = s;
    __syncthreads();
    if (t < 32) {
        float z = (t < 8) ? red[t] : 0.0f;
        #pragma unroll
        for (int o = 4; o; o >>= 1) z += __shfl_xor_sync(0xffffffffu, z, o);
        if (t == 0) s_mean = z * (1.0f / 512.0f);
    }
    __syncthreads();
    const float mean = s_mean;
    const float d0 = v0 - mean, d1 = v1 - mean;

    float qv = d0 * d0 + d1 * d1;
    #pragma unroll
    for (int o = 16; o; o >>= 1) qv += __shfl_xor_sync(0xffffffffu, qv, o);
    if ((t & 31) == 0) red[t >> 5] = qv;
    __syncthreads();
    if (t < 32) {
        float z = (t < 8) ? red[t] : 0.0f;
        #pragma unroll
        for (int o = 4; o; o >>= 1) z += __shfl_xor_sync(0xffffffffu, z, o);
        if (t == 0) s_rstd = rsqrtf(z * (1.0f / 512.0f) + 1e-5f);
    }
    __syncthreads();
    const float rs = s_rstd;
    float y0 = d0 * rs * gw[t]       + bw[t];
    float y1 = d1 * rs * gw[t + 256] + bw[t + 256];
    size_t o0 = (size_t)r * HD + t;
    Out[o0]       = y0;
    Out[o0 + 256] = y1;
    if (SPLIT) {
        bf16 h0 = __float2bfloat16_rn(y0);
        bf16 h1 = __float2bfloat16_rn(y1);
        Oh[o0]       = h0;
        Oh[o0 + 256] = h1;
        Ol[o0]       = __float2bfloat16_rn(y0 - __bfloat162float(h0));
        Ol[o0 + 256] = __float2bfloat16_rn(y1 - __bfloat162float(h1));
    }
}

// ---------------- launch ----------------------------------------------------
extern "C" void kernel_launch(void* const* d_in, const int* in_sizes, int n_in,
                              void* d_out, int out_size)
{
    (void)in_sizes; (void)n_in; (void)out_size;
    const float* query = (const float*)d_in[0];
    const float* key   = (const float*)d_in[1];
    const float* value = (const float*)d_in[2];
    const float* Wq    = (const float*)d_in[3];
    const float* bq    = (const float*)d_in[4];
    const float* Wk    = (const float*)d_in[5];
    const float* bk    = (const float*)d_in[6];
    const float* Wv    = (const float*)d_in[7];
    const float* bv    = (const float*)d_in[8];
    const float* Wo    = (const float*)d_in[9];
    const float* bo    = (const float*)d_in[10];
    const float* ln1_g = (const float*)d_in[11];
    const float* ln1_b = (const float*)d_in[12];
    const float* W1    = (const float*)d_in[13];
    const float* b1    = (const float*)d_in[14];
    const float* W2    = (const float*)d_in[15];
    const float* b2    = (const float*)d_in[16];
    const float* ln2_g = (const float*)d_in[17];
    const float* ln2_b = (const float*)d_in[18];
    float* out = (float*)d_out;

    // resolve scratch addresses
    bf16 *qsh,*qsl,*ksh,*ksl,*vsh,*vsl,*Xh,*Xl,*H1h,*H1l,*FFh,*FFl;
    bf16 *Wqh,*Wql,*Wkh,*Wkl,*Wvh,*Wvl,*Woh,*Wol,*W1h,*W1l,*W2h,*W2l;
    float *Qp,*Kp,*Vp,*Xo,*H1,*Y;
    cudaGetSymbolAddress((void**)&qsh, g_qsh); cudaGetSymbolAddress((void**)&qsl, g_qsl);
    cudaGetSymbolAddress((void**)&ksh, g_ksh); cudaGetSymbolAddress((void**)&ksl, g_ksl);
    cudaGetSymbolAddress((void**)&vsh, g_vsh); cudaGetSymbolAddress((void**)&vsl, g_vsl);
    cudaGetSymbolAddress((void**)&Xh,  g_Xh ); cudaGetSymbolAddress((void**)&Xl,  g_Xl );
    cudaGetSymbolAddress((void**)&H1h, g_H1h); cudaGetSymbolAddress((void**)&H1l, g_H1l);
    cudaGetSymbolAddress((void**)&FFh, g_FFh); cudaGetSymbolAddress((void**)&FFl, g_FFl);
    cudaGetSymbolAddress((void**)&Wqh, g_Wqh); cudaGetSymbolAddress((void**)&Wql, g_Wql);
    cudaGetSymbolAddress((void**)&Wkh, g_Wkh); cudaGetSymbolAddress((void**)&Wkl, g_Wkl);
    cudaGetSymbolAddress((void**)&Wvh, g_Wvh); cudaGetSymbolAddress((void**)&Wvl, g_Wvl);
    cudaGetSymbolAddress((void**)&Woh, g_Woh); cudaGetSymbolAddress((void**)&Wol, g_Wol);
    cudaGetSymbolAddress((void**)&W1h, g_W1h); cudaGetSymbolAddress((void**)&W1l, g_W1l);
    cudaGetSymbolAddress((void**)&W2h, g_W2h); cudaGetSymbolAddress((void**)&W2l, g_W2l);
    cudaGetSymbolAddress((void**)&Qp, g_Qp); cudaGetSymbolAddress((void**)&Kp, g_Kp);
    cudaGetSymbolAddress((void**)&Vp, g_Vp); cudaGetSymbolAddress((void**)&Xo, g_Xo);
    cudaGetSymbolAddress((void**)&H1, g_H1); cudaGetSymbolAddress((void**)&Y,  g_Y);

    constexpr int SMEM = (2 * (2 * 128 * 40 + 2 * 64 * 40)) * 2;  // 61440 bytes
    cudaFuncSetAttribute(gemm_bf16s<false,false,true,false>,
                         cudaFuncAttributeMaxDynamicSharedMemorySize, SMEM);
    cudaFuncSetAttribute(gemm_bf16s<false,true,true,false>,
                         cudaFuncAttributeMaxDynamicSharedMemorySize, SMEM);
    cudaFuncSetAttribute(gemm_bf16s<true,false,false,true>,
                         cudaFuncAttributeMaxDynamicSharedMemorySize, SMEM);

    const dim3 blk(256);
    auto sgrid = [](int n) { return dim3((n / 4 + 255) / 256); };

    // split activations + weights into bf16 hi/lo planes
    split_kernel<<<sgrid(NROWS_Q*HD), blk>>>(query, qsh, qsl, NROWS_Q*HD);
    split_kernel<<<sgrid(NROWS_K*HD), blk>>>(key,   ksh, ksl, NROWS_K*HD);
    split_kernel<<<sgrid(NROWS_K*HD), blk>>>(value, vsh, vsl, NROWS_K*HD);
    split_kernel<<<sgrid(HD*HD),  blk>>>(Wq, Wqh, Wql, HD*HD);
    split_kernel<<<sgrid(HD*HD),  blk>>>(Wk, Wkh, Wkl, HD*HD);
    split_kernel<<<sgrid(HD*HD),  blk>>>(Wv, Wvh, Wvl, HD*HD);
    split_kernel<<<sgrid(HD*HD),  blk>>>(Wo, Woh, Wol, HD*HD);
    split_kernel<<<sgrid(HFF*HD), blk>>>(W1, W1h, W1l, HFF*HD);
    split_kernel<<<sgrid(HD*HFF), blk>>>(W2, W2h, W2l, HD*HFF);

    // projections
    gemm_bf16s<false,false,true,false><<<dim3(HD/64, NROWS_Q/128), blk, SMEM>>>(
        qsh, qsl, Wqh, Wql, bq, nullptr, Qp, nullptr, nullptr, NROWS_Q, HD, HD);
    gemm_bf16s<false,false,true,false><<<dim3(HD/64, NROWS_K/128), blk, SMEM>>>(
        ksh, ksl, Wkh, Wkl, bk, nullptr, Kp, nullptr, nullptr, NROWS_K, HD, HD);
    gemm_bf16s<false,false,true,false><<<dim3(HD/64, NROWS_K/128), blk, SMEM>>>(
        vsh, vsl, Wvh, Wvl, bv, nullptr, Vp, nullptr, nullptr, NROWS_K, HD, HD);

    // attention (softmax over C=8 per head) -> X hi/lo
    attn_kernel<<<NROWS_Q, blk>>>();

    // output projection + residual(query), then LN1 (emits fp32 + hi/lo)
    gemm_bf16s<false,true,true,false><<<dim3(HD/64, NROWS_Q/128), blk, SMEM>>>(
        Xh, Xl, Woh, Wol, bo, query, Xo, nullptr, nullptr, NROWS_Q, HD, HD);
    ln_kernel<true><<<NROWS_Q, blk>>>(Xo, ln1_g, ln1_b, H1, H1h, H1l);

    // FFN1 (ReLU, emits hi/lo only), FFN2 (+residual H1)
    gemm_bf16s<true,false,false,true><<<dim3(HFF/64, NROWS_Q/128), blk, SMEM>>>(
        H1h, H1l, W1h, W1l, b1, nullptr, nullptr, FFh, FFl, NROWS_Q, HFF, HD);
    gemm_bf16s<false,true,true,false><<<dim3(HD/64, NROWS_Q/128), blk, SMEM>>>(
        FFh, FFl, W2h, W2l, b2, H1, Y, nullptr, nullptr, NROWS_Q, HD, HFF);

    // LN2 -> output
    ln_kernel<false><<<NROWS_Q, blk>>>(Y, ln2_g, ln2_b, out, nullptr, nullptr);
}

// round 9
// speedup vs baseline: 4.7942x; 1.9635x over previous
#include <cstdint>
#include <cuda_runtime.h>
#include <cuda_bf16.h>
#include <mma.h>
#include <math.h>

using namespace nvcuda;

// Problem constants (B=4, C=8, F=2048, H=512, Hf=1024, NH=8, dh=64)
#define NROWS_Q 8192
#define NROWS_K 65536
#define HD      512
#define HFF     1024

typedef __nv_bfloat16 bf16;

// ---------------- scratch (device globals; no allocation allowed) -----------
__device__ bf16 g_qsh[(size_t)NROWS_Q * HD];
__device__ bf16 g_qsl[(size_t)NROWS_Q * HD];
__device__ bf16 g_Qph[(size_t)NROWS_Q * HD];
__device__ bf16 g_Qpl[(size_t)NROWS_Q * HD];
__device__ float g_Qp[(size_t)NROWS_Q * HD];
__device__ float g_U  [(size_t)8 * NROWS_Q * HD];      // [head][row][512]
__device__ bf16 g_vbh[(size_t)NROWS_Q * 8 * HD];       // [row][head][512]
__device__ bf16 g_vbl[(size_t)NROWS_Q * 8 * HD];
__device__ bf16 g_Xh [(size_t)NROWS_Q * HD];
__device__ bf16 g_Xl [(size_t)NROWS_Q * HD];
__device__ bf16 g_H1h[(size_t)NROWS_Q * HD];
__device__ bf16 g_H1l[(size_t)NROWS_Q * HD];
__device__ bf16 g_FFh[(size_t)NROWS_Q * HFF];
__device__ bf16 g_FFl[(size_t)NROWS_Q * HFF];
__device__ bf16 g_Wqh[HD*HD],  g_Wql[HD*HD];
__device__ bf16 g_Wkth[HD*HD], g_Wktl[HD*HD];          // transposed Wk planes
__device__ bf16 g_Wvh[HD*HD],  g_Wvl[HD*HD];
__device__ bf16 g_Woh[HD*HD],  g_Wol[HD*HD];
__device__ bf16 g_W1h[HFF*HD], g_W1l[HFF*HD];
__device__ bf16 g_W2h[HD*HFF], g_W2l[HD*HFF];
__device__ float g_Xo[(size_t)NROWS_Q * HD];
__device__ float g_H1[(size_t)NROWS_Q * HD];
__device__ float g_Y [(size_t)NROWS_Q * HD];
__device__ float g_zero[HD];                           // zero bias (zero-init)

// ---------------- helpers ----------------------------------------------------
__device__ __forceinline__ void cp16(void* s, const void* g) {
    unsigned int sa = (unsigned int)__cvta_generic_to_shared(s);
    asm volatile("cp.async.cg.shared.global [%0], [%1], 16;\n" :: "r"(sa), "l"(g));
}
__device__ __forceinline__ void cp_commit() { asm volatile("cp.async.commit_group;\n"); }
template<int N> __device__ __forceinline__ void cp_wait() {
    asm volatile("cp.async.wait_group %0;\n" :: "n"(N));
}

// ---------------- split: fp32 -> bf16 hi/lo ---------------------------------
__global__ __launch_bounds__(256)
void split_kernel(const float* __restrict__ s, bf16* __restrict__ h,
                  bf16* __restrict__ l, int n)
{
    int i = (blockIdx.x * 256 + threadIdx.x) * 4;
    if (i >= n) return;
    float4 v = *reinterpret_cast<const float4*>(s + i);
    bf16 h0 = __float2bfloat16_rn(v.x);
    bf16 h1 = __float2bfloat16_rn(v.y);
    bf16 h2 = __float2bfloat16_rn(v.z);
    bf16 h3 = __float2bfloat16_rn(v.w);
    bf16 l0 = __float2bfloat16_rn(v.x - __bfloat162float(h0));
    bf16 l1 = __float2bfloat16_rn(v.y - __bfloat162float(h1));
    bf16 l2 = __float2bfloat16_rn(v.z - __bfloat162float(h2));
    bf16 l3 = __float2bfloat16_rn(v.w - __bfloat162float(h3));
    __nv_bfloat162 ph0; ph0.x = h0; ph0.y = h1;
    __nv_bfloat162 ph1; ph1.x = h2; ph1.y = h3;
    __nv_bfloat162 pl0; pl0.x = l0; pl0.y = l1;
    __nv_bfloat162 pl1; pl1.x = l2; pl1.y = l3;
    *reinterpret_cast<__nv_bfloat162*>(h + i)     = ph0;
    *reinterpret_cast<__nv_bfloat162*>(h + i + 2) = ph1;
    *reinterpret_cast<__nv_bfloat162*>(l + i)     = pl0;
    *reinterpret_cast<__nv_bfloat162*>(l + i + 2) = pl1;
}

// ---------------- transpose + split: T[p,q] = W[q,p] -> bf16 hi/lo ----------
__global__ __launch_bounds__(256)
void tsplit_kernel(const float* __restrict__ W, bf16* __restrict__ Th,
                   bf16* __restrict__ Tl, int dim)
{
    __shared__ float t[32][33];
    const int bx = blockIdx.x * 32, by = blockIdx.y * 32;
    const int tx = threadIdx.x & 31, ty = threadIdx.x >> 5;
    #pragma unroll
    for (int i = 0; i < 32; i += 8)
        t[ty + i][tx] = W[(size_t)(by + ty + i) * dim + bx + tx];
    __syncthreads();
    #pragma unroll
    for (int i = 0; i < 32; i += 8) {
        float v = t[tx][ty + i];
        bf16 h = __float2bfloat16_rn(v);
        size_t o = (size_t)(bx + ty + i) * dim + by + tx;
        Th[o] = h;
        Tl[o] = __float2bfloat16_rn(v - __bfloat162float(h));
    }
}

// ---------------- bf16-split GEMM (generalized strides + batch) -------------
// C[m,n] = sum_k A[m,k]*W[n,k] + bias[n], hi*hi + hi*lo + lo*hi.
// BM=128, BN=64, BK=32, 256 threads, 8 warps (4Mx2N), 32x32 per warp.
// blockIdx.z = batch; pointers advance by the given element strides.
template<bool RELU, bool RES, bool OUTF, bool SPLIT>
__global__ __launch_bounds__(256)
void gemm_bf16s(const bf16* __restrict__ Ah_, const bf16* __restrict__ Al_,
                int lda, size_t aB,
                const bf16* __restrict__ Wh_, const bf16* __restrict__ Wl_,
                int ldb, size_t wB,
                const float* __restrict__ bias_, size_t biasB,
                const float* __restrict__ res_,
                float* __restrict__ Cout_, bf16* __restrict__ Oh_,
                bf16* __restrict__ Ol_, int ldc, size_t cB, int K)
{
    constexpr int BM = 128, BN = 64, BK = 32;
    constexpr int LDA = 40;
    constexpr int ASZ = BM * LDA;
    constexpr int BSZ = BN * LDA;
    constexpr int STAGE_ELEMS = 2 * ASZ + 2 * BSZ;
    constexpr int LDC = 68;

    extern __shared__ __align__(16) unsigned char smem_raw[];
    bf16* smem = reinterpret_cast<bf16*>(smem_raw);

    const int z = blockIdx.z;
    const bf16* Ah = Ah_ + (size_t)z * aB;
    const bf16* Al = Al_ + (size_t)z * aB;
    const bf16* Wh = Wh_ + (size_t)z * wB;
    const bf16* Wl = Wl_ + (size_t)z * wB;
    const float* bias = bias_ + (size_t)z * biasB;
    const float* res  = RES  ? res_  + (size_t)z * cB : nullptr;
    float* Cout = OUTF ? Cout_ + (size_t)z * cB : nullptr;
    bf16*  Oh   = SPLIT ? Oh_ + (size_t)z * cB : nullptr;
    bf16*  Ol   = SPLIT ? Ol_ + (size_t)z * cB : nullptr;

    const int tid  = threadIdx.x;
    const int warp = tid >> 5;
    const int wm   = warp & 3;
    const int wn   = warp >> 2;
    const int bm0  = blockIdx.y * BM;
    const int bn0  = blockIdx.x * BN;
    const int NK   = K >> 5;

    wmma::fragment<wmma::accumulator, 16, 16, 16, float> acc[2][2];
    #pragma unroll
    for (int i = 0; i < 2; i++)
        #pragma unroll
        for (int j = 0; j < 2; j++)
            wmma::fill_fragment(acc[i][j], 0.0f);

    auto load_stage = [&](int s, int k0) {
        bf16* dAh = smem + s * STAGE_ELEMS;
        bf16* dAl = dAh + ASZ;
        bf16* dBh = dAl + ASZ;
        bf16* dBl = dBh + BSZ;
        #pragma unroll
        for (int t = 0; t < 2; t++) {
            int chunk = tid + t * 256;
            int row = chunk >> 2;
            int c   = (chunk & 3) * 8;
            size_t goff = (size_t)(bm0 + row) * lda + k0 + c;
            cp16(dAh + row * LDA + c, Ah + goff);
            cp16(dAl + row * LDA + c, Al + goff);
        }
        {
            int row = tid >> 2;
            int c   = (tid & 3) * 8;
            size_t goff = (size_t)(bn0 + row) * ldb + k0 + c;
            cp16(dBh + row * LDA + c, Wh + goff);
            cp16(dBl + row * LDA + c, Wl + goff);
        }
    };

    load_stage(0, 0);
    cp_commit();

    for (int kt = 0; kt < NK; kt++) {
        if (kt + 1 < NK) {
            load_stage((kt + 1) & 1, (kt + 1) * BK);
            cp_commit();
            cp_wait<1>();
        } else {
            cp_wait<0>();
        }
        __syncthreads();

        const bf16* sAh = smem + (kt & 1) * STAGE_ELEMS;
        const bf16* sAl = sAh + ASZ;
        const bf16* sBh = sAl + ASZ;
        const bf16* sBl = sBh + BSZ;

        #pragma unroll
        for (int kk = 0; kk < BK; kk += 16) {
            wmma::fragment<wmma::matrix_a, 16, 16, 16, bf16, wmma::row_major> ah[2], al[2];
            wmma::fragment<wmma::matrix_b, 16, 16, 16, bf16, wmma::col_major> bh[2], bl[2];
            #pragma unroll
            for (int i = 0; i < 2; i++) {
                wmma::load_matrix_sync(ah[i], sAh + (wm * 32 + i * 16) * LDA + kk, LDA);
                wmma::load_matrix_sync(al[i], sAl + (wm * 32 + i * 16) * LDA + kk, LDA);
            }
            #pragma unroll
            for (int j = 0; j < 2; j++) {
                wmma::load_matrix_sync(bh[j], sBh + (wn * 32 + j * 16) * LDA + kk, LDA);
                wmma::load_matrix_sync(bl[j], sBl + (wn * 32 + j * 16) * LDA + kk, LDA);
            }
            #pragma unroll
            for (int i = 0; i < 2; i++)
                #pragma unroll
                for (int j = 0; j < 2; j++) {
                    wmma::mma_sync(acc[i][j], ah[i], bh[j], acc[i][j]);
                    wmma::mma_sync(acc[i][j], ah[i], bl[j], acc[i][j]);
                    wmma::mma_sync(acc[i][j], al[i], bh[j], acc[i][j]);
                }
        }
        __syncthreads();
    }

    float* sC = reinterpret_cast<float*>(smem_raw);
    #pragma unroll
    for (int i = 0; i < 2; i++)
        #pragma unroll
        for (int j = 0; j < 2; j++)
            wmma::store_matrix_sync(sC + (wm * 32 + i * 16) * LDC + wn * 32 + j * 16,
                                    acc[i][j], LDC, wmma::mem_row_major);
    __syncthreads();

    for (int idx = tid; idx < BM * BN; idx += 256) {
        int m = idx >> 6;
        int n = idx & 63;
        size_t go = (size_t)(bm0 + m) * ldc + bn0 + n;
        float v = sC[m * LDC + n] + bias[bn0 + n];
        if (RES)  v += res[go];
        if (RELU) v  = fmaxf(v, 0.0f);
        if (OUTF) Cout[go] = v;
        if (SPLIT) {
            bf16 h = __float2bfloat16_rn(v);
            Oh[go] = h;
            Ol[go] = __float2bfloat16_rn(v - __bfloat162float(h));
        }
    }
}

// ---------------- fused attention on RAW k/v ---------------------------------
// Block per query row r, warp per head h.
// s_c = U_h[r]·k_raw[r8+c] + Qp_h[r]·bk_h;  att = softmax(s/8);
// vbar_h[r] = sum_c att_c * v_raw[r8+c]  -> bf16 hi/lo.
__global__ __launch_bounds__(256)
void attn2_kernel(const float* __restrict__ key, const float* __restrict__ value,
                  const float* __restrict__ bk)
{
    __shared__ float ks[8][HD];
    __shared__ float vs[8][HD];

    const int r   = blockIdx.x;
    const int tid = threadIdx.x;
    const int h   = tid >> 5;
    const int l   = tid & 31;

    const float4* kg = reinterpret_cast<const float4*>(key   + (size_t)r * 8 * HD);
    const float4* vg = reinterpret_cast<const float4*>(value + (size_t)r * 8 * HD);
    float4* ks4 = reinterpret_cast<float4*>(&ks[0][0]);
    float4* vs4 = reinterpret_cast<float4*>(&vs[0][0]);
    #pragma unroll
    for (int i = 0; i < 4; i++) {
        ks4[tid + i * 256] = kg[tid + i * 256];
        vs4[tid + i * 256] = vg[tid + i * 256];
    }
    __syncthreads();

    // score bias: Qp_h[r] . bk_h  (64 dims, 2 per lane)
    const float* qp = g_Qp + (size_t)r * HD + h * 64;
    const float* bh = bk + h * 64;
    float sb = qp[l * 2] * bh[l * 2] + qp[l * 2 + 1] * bh[l * 2 + 1];
    #pragma unroll
    for (int o = 16; o; o >>= 1) sb += __shfl_xor_sync(0xffffffffu, sb, o);

    // U row (this head): 16 floats per lane as 4 float4s at j = l*4 + t*128
    const float* Urow = g_U + ((size_t)h * NROWS_Q + r) * HD;
    float4 Uv[4];
    #pragma unroll
    for (int t = 0; t < 4; t++)
        Uv[t] = *reinterpret_cast<const float4*>(Urow + l * 4 + t * 128);

    float s[8];
    #pragma unroll
    for (int c = 0; c < 8; c++) {
        float p = 0.0f;
        #pragma unroll
        for (int t = 0; t < 4; t++) {
            float4 kv = *reinterpret_cast<const float4*>(&ks[c][l * 4 + t * 128]);
            p += Uv[t].x * kv.x + Uv[t].y * kv.y + Uv[t].z * kv.z + Uv[t].w * kv.w;
        }
        #pragma unroll
        for (int o = 16; o; o >>= 1) p += __shfl_xor_sync(0xffffffffu, p, o);
        s[c] = (p + sb) * 0.125f;
    }

    float mx = s[0];
    #pragma unroll
    for (int c = 1; c < 8; c++) mx = fmaxf(mx, s[c]);
    float e[8], sum = 0.0f;
    #pragma unroll
    for (int c = 0; c < 8; c++) { e[c] = expf(s[c] - mx); sum += e[c]; }
    const float inv = 1.0f / sum;

    float4 a4[4];
    #pragma unroll
    for (int t = 0; t < 4; t++) { a4[t].x = a4[t].y = a4[t].z = a4[t].w = 0.0f; }
    #pragma unroll
    for (int c = 0; c < 8; c++) {
        const float a = e[c] * inv;
        #pragma unroll
        for (int t = 0; t < 4; t++) {
            float4 vv = *reinterpret_cast<const float4*>(&vs[c][l * 4 + t * 128]);
            a4[t].x += a * vv.x; a4[t].y += a * vv.y;
            a4[t].z += a * vv.z; a4[t].w += a * vv.w;
        }
    }

    const size_t base = ((size_t)r * 8 + h) * HD + l * 4;
    #pragma unroll
    for (int t = 0; t < 4; t++) {
        bf16 h0 = __float2bfloat16_rn(a4[t].x);
        bf16 h1 = __float2bfloat16_rn(a4[t].y);
        bf16 h2 = __float2bfloat16_rn(a4[t].z);
        bf16 h3 = __float2bfloat16_rn(a4[t].w);
        __nv_bfloat162 hp0; hp0.x = h0; hp0.y = h1;
        __nv_bfloat162 hp1; hp1.x = h2; hp1.y = h3;
        __nv_bfloat162 lp0;
        lp0.x = __float2bfloat16_rn(a4[t].x - __bfloat162float(h0));
        lp0.y = __float2bfloat16_rn(a4[t].y - __bfloat162float(h1));
        __nv_bfloat162 lp1;
        lp1.x = __float2bfloat16_rn(a4[t].z - __bfloat162float(h2));
        lp1.y = __float2bfloat16_rn(a4[t].w - __bfloat162float(h3));
        *reinterpret_cast<__nv_bfloat162*>(g_vbh + base + t * 128)     = hp0;
        *reinterpret_cast<__nv_bfloat162*>(g_vbh + base + t * 128 + 2) = hp1;
        *reinterpret_cast<__nv_bfloat162*>(g_vbl + base + t * 128)     = lp0;
        *reinterpret_cast<__nv_bfloat162*>(g_vbl + base + t * 128 + 2) = lp1;
    }
}

// ---------------- LayerNorm (optionally emits bf16 hi/lo too) ---------------
template<bool SPLIT>
__global__ __launch_bounds__(256)
void ln_kernel(const float* __restrict__ X, const float* __restrict__ gw,
               const float* __restrict__ bw, float* __restrict__ Out,
               bf16* __restrict__ Oh, bf16* __restrict__ Ol)
{
    const int r = blockIdx.x;
    const int t = threadIdx.x;
    const float* x = X + (size_t)r * HD;
    const float v0 = x[t];
    const float v1 = x[t + 256];

    __shared__ float red[8];
    __shared__ float s_mean, s_rstd;

    float s = v0 + v1;
    #pragma unroll
    for (int o = 16; o; o >>= 1) s += __shfl_xor_sync(0xffffffffu, s, o);
    if ((t & 31) == 0) red[t >> 5] = s;
    __syncthreads();
    if (t < 32) {
        float z = (t < 8) ? red[t] : 0.0f;
        #pragma unroll
        for (int o = 4; o; o >>= 1) z += __shfl_xor_sync(0xffffffffu, z, o);
        if (t == 0) s_mean = z * (1.0f / 512.0f);
    }
    __syncthreads();
    const float mean = s_mean;
    const float d0 = v0 - mean, d1 = v1 - mean;

    float qv = d0 * d0 + d1 * d1;
    #pragma unroll
    for (int o = 16; o; o >>= 1) qv += __shfl_xor_sync(0xffffffffu, qv, o);
    if ((t & 31) == 0) red[t >> 5] = qv;
    __syncthreads();
    if (t < 32) {
        float z = (t < 8) ? red[t] : 0.0f;
        #pragma unroll
        for (int o = 4; o; o >>= 1) z += __shfl_xor_sync(0xffffffffu, z, o);
        if (t == 0) s_rstd = rsqrtf(z * (1.0f / 512.0f) + 1e-5f);
    }
    __syncthreads();
    const float rs = s_rstd;
    float y0 = d0 * rs * gw[t]       + bw[t];
    float y1 = d1 * rs * gw[t + 256] + bw[t + 256];
    size_t o0 = (size_t)r * HD + t;
    Out[o0]       = y0;
    Out[o0 + 256] = y1;
    if (SPLIT) {
        bf16 h0 = __float2bfloat16_rn(y0);
        bf16 h1 = __float2bfloat16_rn(y1);
        Oh[o0]       = h0;
        Oh[o0 + 256] = h1;
        Ol[o0]       = __float2bfloat16_rn(y0 - __bfloat162float(h0));
        Ol[o0 + 256] = __float2bfloat16_rn(y1 - __bfloat162float(h1));
    }
}

// ---------------- launch ----------------------------------------------------
extern "C" void kernel_launch(void* const* d_in, const int* in_sizes, int n_in,
                              void* d_out, int out_size)
{
    (void)in_sizes; (void)n_in; (void)out_size;
    const float* query = (const float*)d_in[0];
    const float* key   = (const float*)d_in[1];
    const float* value = (const float*)d_in[2];
    const float* Wq    = (const float*)d_in[3];
    const float* bq    = (const float*)d_in[4];
    const float* Wk    = (const float*)d_in[5];
    const float* bk    = (const float*)d_in[6];
    const float* Wv    = (const float*)d_in[7];
    const float* bv    = (const float*)d_in[8];
    const float* Wo    = (const float*)d_in[9];
    const float* bo    = (const float*)d_in[10];
    const float* ln1_g = (const float*)d_in[11];
    const float* ln1_b = (const float*)d_in[12];
    const float* W1    = (const float*)d_in[13];
    const float* b1    = (const float*)d_in[14];
    const float* W2    = (const float*)d_in[15];
    const float* b2    = (const float*)d_in[16];
    const float* ln2_g = (const float*)d_in[17];
    const float* ln2_b = (const float*)d_in[18];
    float* out = (float*)d_out;

    bf16 *qsh,*qsl,*Qph,*Qpl,*vbh,*vbl,*Xh,*Xl,*H1h,*H1l,*FFh,*FFl;
    bf16 *Wqh,*Wql,*Wkth,*Wktl,*Wvh,*Wvl,*Woh,*Wol,*W1h,*W1l,*W2h,*W2l;
    float *Qp,*U,*Xo,*H1,*Y,*zero;
    cudaGetSymbolAddress((void**)&qsh, g_qsh);  cudaGetSymbolAddress((void**)&qsl, g_qsl);
    cudaGetSymbolAddress((void**)&Qph, g_Qph);  cudaGetSymbolAddress((void**)&Qpl, g_Qpl);
    cudaGetSymbolAddress((void**)&vbh, g_vbh);  cudaGetSymbolAddress((void**)&vbl, g_vbl);
    cudaGetSymbolAddress((void**)&Xh,  g_Xh );  cudaGetSymbolAddress((void**)&Xl,  g_Xl );
    cudaGetSymbolAddress((void**)&H1h, g_H1h);  cudaGetSymbolAddress((void**)&H1l, g_H1l);
    cudaGetSymbolAddress((void**)&FFh, g_FFh);  cudaGetSymbolAddress((void**)&FFl, g_FFl);
    cudaGetSymbolAddress((void**)&Wqh, g_Wqh);  cudaGetSymbolAddress((void**)&Wql, g_Wql);
    cudaGetSymbolAddress((void**)&Wkth,g_Wkth); cudaGetSymbolAddress((void**)&Wktl,g_Wktl);
    cudaGetSymbolAddress((void**)&Wvh, g_Wvh);  cudaGetSymbolAddress((void**)&Wvl, g_Wvl);
    cudaGetSymbolAddress((void**)&Woh, g_Woh);  cudaGetSymbolAddress((void**)&Wol, g_Wol);
    cudaGetSymbolAddress((void**)&W1h, g_W1h);  cudaGetSymbolAddress((void**)&W1l, g_W1l);
    cudaGetSymbolAddress((void**)&W2h, g_W2h);  cudaGetSymbolAddress((void**)&W2l, g_W2l);
    cudaGetSymbolAddress((void**)&Qp, g_Qp);    cudaGetSymbolAddress((void**)&U,  g_U);
    cudaGetSymbolAddress((void**)&Xo, g_Xo);    cudaGetSymbolAddress((void**)&H1, g_H1);
    cudaGetSymbolAddress((void**)&Y,  g_Y);     cudaGetSymbolAddress((void**)&zero, g_zero);

    constexpr int SMEM = (2 * (2 * 128 * 40 + 2 * 64 * 40)) * 2;  // 61440 bytes
    cudaFuncSetAttribute(gemm_bf16s<false,false,true,true>,
                         cudaFuncAttributeMaxDynamicSharedMemorySize, SMEM);
    cudaFuncSetAttribute(gemm_bf16s<false,false,true,false>,
                         cudaFuncAttributeMaxDynamicSharedMemorySize, SMEM);
    cudaFuncSetAttribute(gemm_bf16s<false,false,false,true>,
                         cudaFuncAttributeMaxDynamicSharedMemorySize, SMEM);
    cudaFuncSetAttribute(gemm_bf16s<false,true,true,false>,
                         cudaFuncAttributeMaxDynamicSharedMemorySize, SMEM);
    cudaFuncSetAttribute(gemm_bf16s<true,false,false,true>,
                         cudaFuncAttributeMaxDynamicSharedMemorySize, SMEM);

    const dim3 blk(256);
    auto sgrid = [](int n) { return dim3((n / 4 + 255) / 256); };

    // operand prep: query split, weight splits, Wk transpose-split
    split_kernel<<<sgrid(NROWS_Q*HD), blk>>>(query, qsh, qsl, NROWS_Q*HD);
    split_kernel<<<sgrid(HD*HD),  blk>>>(Wq, Wqh, Wql, HD*HD);
    split_kernel<<<sgrid(HD*HD),  blk>>>(Wv, Wvh, Wvl, HD*HD);
    split_kernel<<<sgrid(HD*HD),  blk>>>(Wo, Woh, Wol, HD*HD);
    split_kernel<<<sgrid(HFF*HD), blk>>>(W1, W1h, W1l, HFF*HD);
    split_kernel<<<sgrid(HD*HFF), blk>>>(W2, W2h, W2l, HD*HFF);
    tsplit_kernel<<<dim3(HD/32, HD/32), blk>>>(Wk, Wkth, Wktl, HD);

    // Qp = query @ Wq^T + bq  (fp32 + bf16 split out)
    gemm_bf16s<false,false,true,true><<<dim3(HD/64, NROWS_Q/128, 1), blk, SMEM>>>(
        qsh, qsl, HD, 0,  Wqh, Wql, HD, 0,  bq, 0,  nullptr,
        Qp, Qph, Qpl, HD, 0, HD);

    // U_h = Qp_h @ Wkt_h  (8 batched GEMMs, K=64) -> U [head][row][512]
    gemm_bf16s<false,false,true,false><<<dim3(HD/64, NROWS_Q/128, 8), blk, SMEM>>>(
        Qph, Qpl, HD, 64,  Wkth, Wktl, HD, 64,  zero, 0,  nullptr,
        U, nullptr, nullptr, HD, (size_t)NROWS_Q * HD, 64);

    // fused attention on raw k/v -> vbar hi/lo
    attn2_kernel<<<NROWS_Q, blk>>>(key, value, bk);

    // x_h = vbar_h @ Wv_h^T + bv_h  (8 batched GEMMs) -> X hi/lo
    gemm_bf16s<false,false,false,true><<<dim3(1, NROWS_Q/128, 8), blk, SMEM>>>(
        vbh, vbl, 8*HD, HD,  Wvh, Wvl, HD, (size_t)64*HD,  bv, 64,  nullptr,
        nullptr, Xh, Xl, HD, 64, HD);

    // output projection + residual(query), then LN1
    gemm_bf16s<false,true,true,false><<<dim3(HD/64, NROWS_Q/128, 1), blk, SMEM>>>(
        Xh, Xl, HD, 0,  Woh, Wol, HD, 0,  bo, 0,  query,
        Xo, nullptr, nullptr, HD, 0, HD);
    ln_kernel<true><<<NROWS_Q, blk>>>(Xo, ln1_g, ln1_b, H1, H1h, H1l);

    // FFN1 (ReLU, bf16 hi/lo out), FFN2 (+residual H1)
    gemm_bf16s<true,false,false,true><<<dim3(HFF/64, NROWS_Q/128, 1), blk, SMEM>>>(
        H1h, H1l, HD, 0,  W1h, W1l, HD, 0,  b1, 0,  nullptr,
        nullptr, FFh, FFl, HFF, 0, HD);
    gemm_bf16s<false,true,true,false><<<dim3(HD/64, NROWS_Q/128, 1), blk, SMEM>>>(
        FFh, FFl, HFF, 0,  W2h, W2l, HFF, 0,  b2, 0,  H1,
        Y, nullptr, nullptr, HD, 0, HFF);

    // LN2 -> output
    ln_kernel<false><<<NROWS_Q, blk>>>(Y, ln2_g, ln2_b, out, nullptr, nullptr);
}